// round 15
// baseline (speedup 1.0000x reference)
#include <cuda_runtime.h>
#include <cuda_fp16.h>
#include <cstdint>

// ---------------------------------------------------------------------------
// DenseGCN (3-layer GraphSAGE, mean aggr) on GB300.
//   - matmul BEFORE mean-aggregation (linearity).
//   - CSR: histogram folded into conversion kernel, parallel scans,
//     vectorized scatter. Single stream.
//   - gather-side fp16 aggregation, fp32 accumulation. Layers 2/3 use
//     paired-lane gathers (2 neighbors/warp-iter, 16B/lane, shfl combine).
//   - GEMMs: fp16 mma.sync m16n8k16, 2-term weight split (W=Wh+Wl),
//     cp.async double-buffer + ldmatrix, term-major ordering, 2 CTA/SM.
//     (tcgen05 is NOT available: harness PTX targets compute_103 sans 'a'.)
//   - layer-1 projection + SAGE GEMM fused (N=192, split epilogue).
// ---------------------------------------------------------------------------

#define NMAX 50176
#define EMAX 1000448
#define SCAN_B 1024

__device__ __align__(16) __half g_Yh[(size_t)NMAX * 256];
__device__ __align__(16) __half g_Xh[(size_t)NMAX * 64];
__device__ __align__(16) __half g_Fh[(size_t)NMAX * 256];
__device__ __align__(16) __half g_Wh[110592];
__device__ __align__(16) __half g_Wlo[110592];
__device__ int g_row_off[NMAX + 1];
__device__ int g_cnt[NMAX];
__device__ int g_bsum[64];
__device__ int g_src_sorted[EMAX];
__device__ int g_is64;

#define WOFF_PL1 0
#define WOFF_2   12288
#define WOFF_3   45056
#define WTOT     110592

// --------------------------- PTX helpers -----------------------------------
__device__ __forceinline__ void ldm4(unsigned* r, uint32_t addr) {
    asm volatile("ldmatrix.sync.aligned.m8n8.x4.shared.b16 {%0,%1,%2,%3}, [%4];"
                 : "=r"(r[0]), "=r"(r[1]), "=r"(r[2]), "=r"(r[3]) : "r"(addr));
}
__device__ __forceinline__ void cp16(uint32_t d, const void* s, bool p) {
    asm volatile("cp.async.cg.shared.global [%0], [%1], 16, %2;"
                 :: "r"(d), "l"(s), "r"(p ? 16 : 0) : "memory");
}
__device__ __forceinline__ void cpcommit() {
    asm volatile("cp.async.commit_group;" ::: "memory");
}
__device__ __forceinline__ void mma16816(float* c, const unsigned* a,
                                         unsigned b0, unsigned b1) {
    asm volatile(
        "mma.sync.aligned.m16n8k16.row.col.f32.f16.f16.f32 "
        "{%0,%1,%2,%3}, {%4,%5,%6,%7}, {%8,%9}, {%0,%1,%2,%3};"
        : "+f"(c[0]), "+f"(c[1]), "+f"(c[2]), "+f"(c[3])
        : "r"(a[0]), "r"(a[1]), "r"(a[2]), "r"(a[3]), "r"(b0), "r"(b1));
}

// --------------------------- CSR prep --------------------------------------
__global__ void zero_cnt(int n) {
    int i = blockIdx.x * blockDim.x + threadIdx.x;
    if (i < n) g_cnt[i] = 0;
}

// ------ conversion (weights + x) + edge histogram + dtype detect -----------
__global__ void cvt_hist(const float* __restrict__ x, int nx,
                         const void* __restrict__ ev, int E,
                         const float* __restrict__ Wp,
                         const float* __restrict__ Wl1, const float* __restrict__ Wr1,
                         const float* __restrict__ Wl2, const float* __restrict__ Wr2,
                         const float* __restrict__ Wl3, const float* __restrict__ Wr3) {
    int i = blockIdx.x * blockDim.x + threadIdx.x;
    const unsigned int* eu = (const unsigned int*)ev;
    if (i < E) {
        int is64 = 1;
#pragma unroll
        for (int q = 0; q < 8; q++)
            if (eu[2 * q + 1] != 0u) is64 = 0;
        if (i == 0) g_is64 = is64;
        int dst;
        if (is64) dst = (int)((const long long*)ev)[(size_t)E + i];
        else      dst = ((const int*)ev)[E + i];
        atomicAdd(&g_cnt[dst], 1);
    }
    if (i < WTOT) {
        float w;
        if (i < 12288) {
            int n = i / 64, k = i % 64;
            if (n < 64)       w = Wp[k * 64 + n];
            else if (n < 128) w = Wl1[k * 64 + (n - 64)];
            else              w = Wr1[k * 64 + (n - 128)];
        } else if (i < 45056) {
            int j = i - WOFF_2;
            int n = j / 128, k = j % 128;
            w = (n < 128) ? Wl2[k * 128 + n] : Wr2[k * 128 + (n - 128)];
        } else {
            int j = i - WOFF_3;
            int n = j / 256, k = j % 256;
            w = (n < 128) ? Wl3[k * 128 + n] : Wr3[k * 128 + (n - 128)];
        }
        __half hi = __float2half_rn(w);
        g_Wh[i]  = hi;
        g_Wlo[i] = __float2half_rn(w - __half2float(hi));
    } else {
        int j = i - WTOT;
        if (j < nx) g_Xh[j] = __float2half_rn(x[j]);
    }
}

__global__ void __launch_bounds__(SCAN_B) scan_blocks(int n) {
    __shared__ int wsum[32];
    int tid = threadIdx.x;
    int lane = tid & 31, wid = tid >> 5;
    int i = blockIdx.x * SCAN_B + tid;
    int v = (i < n) ? g_cnt[i] : 0;
    int incl = v;
#pragma unroll
    for (int off = 1; off < 32; off <<= 1) {
        int t = __shfl_up_sync(0xffffffffu, incl, off);
        if (lane >= off) incl += t;
    }
    if (lane == 31) wsum[wid] = incl;
    __syncthreads();
    if (wid == 0) {
        int w = wsum[lane];
#pragma unroll
        for (int off = 1; off < 32; off <<= 1) {
            int t = __shfl_up_sync(0xffffffffu, w, off);
            if (lane >= off) w += t;
        }
        wsum[lane] = w;
    }
    __syncthreads();
    int add = (wid > 0) ? wsum[wid - 1] : 0;
    int excl = add + incl - v;
    if (i < n) g_row_off[i] = excl;
    if (tid == SCAN_B - 1) g_bsum[blockIdx.x] = add + incl;
}

__global__ void scan_bsum(int nb) {
    __shared__ int w0;
    int tid = threadIdx.x;
    int lane = tid & 31;
    int v = (tid < nb) ? g_bsum[tid] : 0;
    int incl = v;
#pragma unroll
    for (int off = 1; off < 32; off <<= 1) {
        int t = __shfl_up_sync(0xffffffffu, incl, off);
        if (lane >= off) incl += t;
    }
    if (tid == 31) w0 = incl;
    __syncthreads();
    int add = (tid >= 32) ? w0 : 0;
    int excl = add + incl - v;
    if (tid < nb) g_bsum[tid] = excl;
}

__global__ void __launch_bounds__(SCAN_B) scan_add(int n, int E) {
    int i = blockIdx.x * SCAN_B + threadIdx.x;
    if (i < n) {
        int v = g_row_off[i] + g_bsum[blockIdx.x];
        g_row_off[i] = v;
        g_cnt[i] = v;
    }
    if (blockIdx.x == 0 && threadIdx.x == 0) g_row_off[n] = E;
}

__global__ void scatter_kernel(const void* e, int E) {
    int i = (blockIdx.x * blockDim.x + threadIdx.x) * 2;
    if (i >= E) return;
    bool two = (i + 1 < E);
    int s0, s1, d0, d1;
    if (g_is64) {
        if (two) {
            longlong2 s = *(const longlong2*)&((const long long*)e)[i];
            longlong2 d = *(const longlong2*)&((const long long*)e)[(size_t)E + i];
            s0 = (int)s.x; s1 = (int)s.y; d0 = (int)d.x; d1 = (int)d.y;
        } else {
            s0 = (int)((const long long*)e)[i];
            d0 = (int)((const long long*)e)[(size_t)E + i];
            s1 = d1 = -1;
        }
    } else {
        if (two) {
            int2 s = *(const int2*)&((const int*)e)[i];
            int2 d = *(const int2*)&((const int*)e)[E + i];
            s0 = s.x; s1 = s.y; d0 = d.x; d1 = d.y;
        } else {
            s0 = ((const int*)e)[i];
            d0 = ((const int*)e)[E + i];
            s1 = d1 = -1;
        }
    }
    int p0 = atomicAdd(&g_cnt[d0], 1);
    g_src_sorted[p0] = s0;
    if (two) {
        int p1 = atomicAdd(&g_cnt[d1], 1);
        g_src_sorted[p1] = s1;
    }
}

// --------------------------- tensor-core GEMM ------------------------------
#define SROWB 80
#define ARRB  10240
#define STAGEB 30720
#define GEMM_SMEM (2 * STAGEB)

__global__ void __launch_bounds__(256, 2) gemm_tc_kernel(
    const __half* __restrict__ Ag, int lda,
    const __half* __restrict__ Wh, const __half* __restrict__ Wl,
    const float* __restrict__ bias,
    __half* __restrict__ C1, __half* __restrict__ C2,
    int ldc, int coff, int ldc2, int M, int N, int K, int mode)
{
    extern __shared__ __align__(16) char smem_raw[];
    uint32_t sb0 = (uint32_t)__cvta_generic_to_shared(smem_raw);
    int tid = threadIdx.x, lane = tid & 31, wid = tid >> 5;
    int wm = wid & 3, wn = wid >> 2;
    int g = lane >> 2, t4 = lane & 3;
    int m0 = blockIdx.x << 7, n0 = blockIdx.y << 7;

    uint32_t arowoff[2];
#pragma unroll
    for (int mi = 0; mi < 2; mi++) {
        int r = (wm << 5) + (mi << 4) + (lane & 7) + (((lane >> 3) & 1) << 3);
        arowoff[mi] = (uint32_t)r * SROWB + ((lane >> 4) << 4);
    }
    uint32_t boff[4];
#pragma unroll
    for (int p = 0; p < 4; p++) {
        int r = (wn << 6) + (p << 4) + (lane & 7) + ((lane >> 4) << 3);
        boff[p] = (uint32_t)r * SROWB + (((lane >> 3) & 1) << 4);
    }

    float acc[2][8][4];
#pragma unroll
    for (int mi = 0; mi < 2; mi++)
#pragma unroll
        for (int ni = 0; ni < 8; ni++)
#pragma unroll
            for (int q = 0; q < 4; q++) acc[mi][ni][q] = 0.f;

    auto stage = [&](int kt, int s) {
        int k0 = kt << 5;
        uint32_t sb = sb0 + (uint32_t)s * STAGEB;
#pragma unroll
        for (int h = 0; h < 2; h++) {
            int c = tid + (h << 8);
            int row = c >> 2, part = c & 3;
            uint32_t soff = (uint32_t)row * SROWB + (part << 4);
            int am = m0 + row;
            bool av = am < M; if (!av) am = 0;
            cp16(sb + soff, Ag + (size_t)am * lda + k0 + (part << 3), av);
            int bn = n0 + row;
            bool bv = bn < N; if (!bv) bn = 0;
            size_t woff = (size_t)bn * K + k0 + (part << 3);
            cp16(sb + ARRB + soff,     Wh + woff, bv);
            cp16(sb + 2 * ARRB + soff, Wl + woff, bv);
        }
        cpcommit();
    };

    int KT = K >> 5;
    stage(0, 0);
    for (int kt = 0; kt < KT; kt++) {
        int s = kt & 1;
        if (kt + 1 < KT) {
            stage(kt + 1, s ^ 1);
            asm volatile("cp.async.wait_group 1;" ::: "memory");
        } else {
            asm volatile("cp.async.wait_group 0;" ::: "memory");
        }
        __syncthreads();
        uint32_t sb = sb0 + (uint32_t)s * STAGEB;
#pragma unroll
        for (int ks = 0; ks < 2; ks++) {
            uint32_t ko = (uint32_t)ks << 5;
            unsigned ah[2][4];
            ldm4(ah[0], sb + arowoff[0] + ko);
            ldm4(ah[1], sb + arowoff[1] + ko);
#pragma unroll
            for (int p = 0; p < 4; p++) {
                unsigned bh[4], bl[4];
                ldm4(bh, sb + ARRB + boff[p] + ko);
                ldm4(bl, sb + 2 * ARRB + boff[p] + ko);
                mma16816(acc[0][2 * p],     ah[0], bh[0], bh[1]);
                mma16816(acc[0][2 * p + 1], ah[0], bh[2], bh[3]);
                mma16816(acc[1][2 * p],     ah[1], bh[0], bh[1]);
                mma16816(acc[1][2 * p + 1], ah[1], bh[2], bh[3]);

                mma16816(acc[0][2 * p],     ah[0], bl[0], bl[1]);
                mma16816(acc[0][2 * p + 1], ah[0], bl[2], bl[3]);
                mma16816(acc[1][2 * p],     ah[1], bl[0], bl[1]);
                mma16816(acc[1][2 * p + 1], ah[1], bl[2], bl[3]);
            }
        }
        __syncthreads();
    }

    bool split = (mode & 2) != 0;
    bool relu = (mode & 1) != 0;
#pragma unroll
    for (int mi = 0; mi < 2; mi++) {
#pragma unroll
        for (int ni = 0; ni < 8; ni++) {
            int row = m0 + (wm << 5) + (mi << 4) + g;
            int col = n0 + (wn << 6) + (ni << 3) + (t4 << 1);
            if (col >= N) continue;
#pragma unroll
            for (int hh = 0; hh < 2; hh++) {
                int r = row + hh * 8;
                if (r >= M) continue;
                float vx = acc[mi][ni][2 * hh];
                float vy = acc[mi][ni][2 * hh + 1];
                if (split) {
                    if (col < 64) {
                        vx = fmaxf(vx + bias[col], 0.f);
                        vy = fmaxf(vy + bias[col + 1], 0.f);
                        *(__half2*)&C1[(size_t)r * ldc + coff + col] =
                            __halves2half2(__float2half_rn(vx),
                                           __float2half_rn(vy));
                    } else {
                        *(__half2*)&C2[(size_t)r * ldc2 + (col - 64)] =
                            __halves2half2(__float2half_rn(vx),
                                           __float2half_rn(vy));
                    }
                } else {
                    if (bias) { vx += bias[col]; vy += bias[col + 1]; }
                    if (relu) { vx = fmaxf(vx, 0.f); vy = fmaxf(vy, 0.f); }
                    *(__half2*)&C1[(size_t)r * ldc + coff + col] =
                        __halves2half2(__float2half_rn(vx),
                                       __float2half_rn(vy));
                }
            }
        }
    }
}

// ---------------- aggregation, 128B rows (layer 1, V=2) --------------------
template <int V>
__global__ void agg_h_kernel(const __half* __restrict__ Y, int ldy, int ycol,
                             int rcol, const float* __restrict__ bias,
                             float* __restrict__ Of, __half* __restrict__ Oh,
                             int ldo, int ocol, int Nn)
{
    int gw = (blockIdx.x * blockDim.x + threadIdx.x) >> 5;
    int lane = threadIdx.x & 31;
    if (gw >= Nn) return;
    int s0 = g_row_off[gw], s1 = g_row_off[gw + 1];
    int col = lane * V;
    float acc[V];
#pragma unroll
    for (int v = 0; v < V; v++) acc[v] = 0.f;
    const __half* Yb = Y + ycol + col;

    auto addrow = [&](const __half* p) {
        if (V == 4) {
            uint2 u = *(const uint2*)p;
            float2 f0 = __half22float2(*(__half2*)&u.x);
            float2 f1 = __half22float2(*(__half2*)&u.y);
            acc[0] += f0.x; acc[1] += f0.y; acc[2] += f1.x; acc[3] += f1.y;
        } else {
            float2 f = __half22float2(*(const __half2*)p);
            acc[0] += f.x; acc[1] += f.y;
        }
    };

    int j = s0;
    for (; j + 7 < s1; j += 8) {
        int s[8];
#pragma unroll
        for (int q = 0; q < 8; q++) s[q] = g_src_sorted[j + q];
#pragma unroll
        for (int q = 0; q < 8; q++) addrow(Yb + (size_t)s[q] * ldy);
    }
    for (; j + 3 < s1; j += 4) {
        int s[4];
#pragma unroll
        for (int q = 0; q < 4; q++) s[q] = g_src_sorted[j + q];
#pragma unroll
        for (int q = 0; q < 4; q++) addrow(Yb + (size_t)s[q] * ldy);
    }
    for (; j < s1; j++) addrow(Yb + (size_t)g_src_sorted[j] * ldy);

    int deg = s1 - s0;
    float inv = 1.f / (float)(deg > 1 ? deg : 1);

    float rterm[V];
    {
        const __half* p = Y + (size_t)gw * ldy + rcol + col;
        if (V == 4) {
            uint2 u = *(const uint2*)p;
            float2 f0 = __half22float2(*(__half2*)&u.x);
            float2 f1 = __half22float2(*(__half2*)&u.y);
            rterm[0] = f0.x; rterm[1] = f0.y; rterm[2] = f1.x; rterm[3] = f1.y;
        } else {
            float2 f = __half22float2(*(const __half2*)p);
            rterm[0] = f.x; rterm[1] = f.y;
        }
    }

    float o[V];
#pragma unroll
    for (int v = 0; v < V; v++)
        o[v] = fmaxf(acc[v] * inv + rterm[v] + bias[col + v], 0.f);

    size_t off = (size_t)gw * ldo + ocol + col;
    if (Oh) {
#pragma unroll
        for (int v = 0; v < V; v += 2)
            *(__half2*)&Oh[off + v] =
                __halves2half2(__float2half_rn(o[v]), __float2half_rn(o[v + 1]));
    } else {
        if (V == 4)
            *(float4*)&Of[off] = make_float4(o[0], o[1], o[2], o[3]);
        else
            *(float2*)&Of[off] = make_float2(o[0], o[1]);
    }
}

// -------- paired-lane aggregation, 256B rows (layers 2/3) ------------------
// Lanes 0-15 process even neighbors, 16-31 odd; each lane loads uint4
// (8 halves) at col (lane&15)*8; final shfl_xor(16) combines halves.
__global__ void agg_h4p_kernel(const __half* __restrict__ Y, int ldy,
                               int rcol, const float* __restrict__ bias,
                               float* __restrict__ Of, __half* __restrict__ Oh,
                               int ldo, int ocol, int Nn)
{
    int gw = (blockIdx.x * blockDim.x + threadIdx.x) >> 5;
    int lane = threadIdx.x & 31;
    if (gw >= Nn) return;
    int s0 = g_row_off[gw], s1 = g_row_off[gw + 1];
    int half_id = lane >> 4;
    int sub = lane & 15;
    int col = sub << 3;          // 8 halves per lane
    float acc[8];
#pragma unroll
    for (int v = 0; v < 8; v++) acc[v] = 0.f;
    const __half* Yb = Y + col;  // ycol = 0 for both layers

    auto addrow = [&](int s) {
        uint4 u = *(const uint4*)(Yb + (size_t)s * ldy);
        float2 a0 = __half22float2(*(__half2*)&u.x);
        float2 a1 = __half22float2(*(__half2*)&u.y);
        float2 a2 = __half22float2(*(__half2*)&u.z);
        float2 a3 = __half22float2(*(__half2*)&u.w);
        acc[0] += a0.x; acc[1] += a0.y; acc[2] += a1.x; acc[3] += a1.y;
        acc[4] += a2.x; acc[5] += a2.y; acc[6] += a3.x; acc[7] += a3.y;
    };

    int j = s0 + half_id;        // this half's first neighbor (stride 2)
    for (; j + 6 < s1; j += 8) { // 4 rows per half per iteration
        int i0 = g_src_sorted[j];
        int i1 = g_src_sorted[j + 2];
        int i2 = g_src_sorted[j + 4];
        int i3 = g_src_sorted[j + 6];
        addrow(i0); addrow(i1); addrow(i2); addrow(i3);
    }
    for (; j < s1; j += 2) addrow(g_src_sorted[j]);

    // combine the two lane-halves
#pragma unroll
    for (int v = 0; v < 8; v++)
        acc[v] += __shfl_xor_sync(0xffffffffu, acc[v], 16);

    if (half_id) return;         // lanes 0-15 finish up

    int deg = s1 - s0;
    float inv = 1.f / (float)(deg > 1 ? deg : 1);

    float r[8];
    {
        uint4 u = *(const uint4*)(Y + (size_t)gw * ldy + rcol + col);
        float2 a0 = __half22float2(*(__half2*)&u.x);
        float2 a1 = __half22float2(*(__half2*)&u.y);
        float2 a2 = __half22float2(*(__half2*)&u.z);
        float2 a3 = __half22float2(*(__half2*)&u.w);
        r[0] = a0.x; r[1] = a0.y; r[2] = a1.x; r[3] = a1.y;
        r[4] = a2.x; r[5] = a2.y; r[6] = a3.x; r[7] = a3.y;
    }

    float o[8];
#pragma unroll
    for (int v = 0; v < 8; v++)
        o[v] = fmaxf(acc[v] * inv + r[v] + bias[col + v], 0.f);

    size_t off = (size_t)gw * ldo + ocol + col;
    if (Oh) {
        uint4 u;
        *(__half2*)&u.x = __halves2half2(__float2half_rn(o[0]), __float2half_rn(o[1]));
        *(__half2*)&u.y = __halves2half2(__float2half_rn(o[2]), __float2half_rn(o[3]));
        *(__half2*)&u.z = __halves2half2(__float2half_rn(o[4]), __float2half_rn(o[5]));
        *(__half2*)&u.w = __halves2half2(__float2half_rn(o[6]), __float2half_rn(o[7]));
        *(uint4*)&Oh[off] = u;
    } else {
        *(float4*)&Of[off]     = make_float4(o[0], o[1], o[2], o[3]);
        *(float4*)&Of[off + 4] = make_float4(o[4], o[5], o[6], o[7]);
    }
}

// ------------------------------- launcher ----------------------------------
extern "C" void kernel_launch(void* const* d_in, const int* in_sizes, int n_in,
                              void* d_out, int out_size)
{
    const float* x   = (const float*)d_in[0];
    const void*  eix = d_in[1];
    const float* Wp  = (const float*)d_in[2];
    const float* bp  = (const float*)d_in[3];
    const float* Wl1 = (const float*)d_in[4];
    const float* bl1 = (const float*)d_in[5];
    const float* Wr1 = (const float*)d_in[6];
    const float* Wl2 = (const float*)d_in[7];
    const float* bl2 = (const float*)d_in[8];
    const float* Wr2 = (const float*)d_in[9];
    const float* Wl3 = (const float*)d_in[10];
    const float* bl3 = (const float*)d_in[11];
    const float* Wr3 = (const float*)d_in[12];

    int N = in_sizes[0] / 64;
    int E = in_sizes[1] / 2;
    float* out = (float*)d_out;

    __half *dYh, *dXh, *dFh, *dWh, *dWlo;
    cudaGetSymbolAddress((void**)&dYh, g_Yh);
    cudaGetSymbolAddress((void**)&dXh, g_Xh);
    cudaGetSymbolAddress((void**)&dFh, g_Fh);
    cudaGetSymbolAddress((void**)&dWh, g_Wh);
    cudaGetSymbolAddress((void**)&dWlo, g_Wlo);

    cudaFuncSetAttribute(gemm_tc_kernel,
                         cudaFuncAttributeMaxDynamicSharedMemorySize,
                         GEMM_SMEM);

    int nb = (N + SCAN_B - 1) / SCAN_B;
    int mg = (N + 127) / 128;
    int ne2 = (E + 1) / 2;

    // ---- counter zeroing, then conversions + histogram (overlapped) ----
    zero_cnt<<<(N + 255) / 256, 256>>>(N);
    int ncvt = WTOT + N * 64;
    if (ncvt < E) ncvt = E;
    cvt_hist<<<(ncvt + 255) / 256, 256>>>(x, N * 64, eix, E,
                                          Wp, Wl1, Wr1, Wl2, Wr2, Wl3, Wr3);

    // ---- fused layer-1 GEMM: [xp | y1 | r1] = x @ [Wp|Wl1|Wr1], N=192 ----
    gemm_tc_kernel<<<dim3(mg, 2), 256, GEMM_SMEM>>>(
        dXh, 64, dWh + WOFF_PL1, dWlo + WOFF_PL1, bp,
        dFh, dYh, 256, 0, 256, N, 192, 64, 2);

    // ---- CSR scans + scatter ----
    scan_blocks<<<nb, SCAN_B>>>(N);
    scan_bsum<<<1, 64>>>(nb);
    scan_add<<<nb, SCAN_B>>>(N, E);
    scatter_kernel<<<(ne2 + 255) / 256, 256>>>(eix, E);

    // ---- layer 1 aggregation -> Fh[:,64:128] ----
    agg_h_kernel<2><<<(N + 7) / 8, 256>>>(dYh, 256, 0, 64, bl1,
                                          nullptr, dFh, 256, 64, N);

    // ---- layer 2 ----
    gemm_tc_kernel<<<dim3(mg, 2), 256, GEMM_SMEM>>>(
        dFh, 256, dWh + WOFF_2, dWlo + WOFF_2, nullptr,
        dYh, nullptr, 256, 0, 0, N, 256, 128, 0);
    agg_h4p_kernel<<<(N + 7) / 8, 256>>>(dYh, 256, 128, bl2,
                                         nullptr, dFh, 256, 128, N);

    // ---- layer 3 ----
    gemm_tc_kernel<<<dim3(mg, 2), 256, GEMM_SMEM>>>(
        dFh, 256, dWh + WOFF_3, dWlo + WOFF_3, nullptr,
        dYh, nullptr, 256, 0, 0, N, 256, 256, 0);
    agg_h4p_kernel<<<(N + 7) / 8, 256>>>(dYh, 256, 128, bl3,
                                         out, nullptr, 128, 0, N);
}

// round 17
// speedup vs baseline: 1.0326x; 1.0326x over previous
#include <cuda_runtime.h>
#include <cuda_fp16.h>
#include <cstdint>

// ---------------------------------------------------------------------------
// DenseGCN (3-layer GraphSAGE, mean aggr) on GB300.
//   - matmul BEFORE mean-aggregation (linearity).
//   - CSR: histogram folded into conversion kernel; SINGLE-PASS scan with
//     parallel aggregate lookback (49 co-resident blocks); vectorized scatter.
//   - g_cnt / scan flags re-zeroed by the tail of the final agg kernel
//     (zero at module load for the first run) -> no zero_cnt launch.
//   - gather-side fp16 aggregation (8/4-way unroll), fp32 accumulation.
//   - GEMMs: fp16 mma.sync m16n8k16, 2-term weight split (W=Wh+Wl),
//     cp.async double-buffer + ldmatrix, term-major ordering, 2 CTA/SM.
//     (tcgen05 unavailable: harness PTX targets compute_103 sans 'a'.)
//   - layer-1 projection + SAGE GEMM fused (N=192, split epilogue).
// ---------------------------------------------------------------------------

#define NMAX 50176
#define EMAX 1000448
#define SCAN_B 1024

__device__ __align__(16) __half g_Yh[(size_t)NMAX * 256];
__device__ __align__(16) __half g_Xh[(size_t)NMAX * 64];
__device__ __align__(16) __half g_Fh[(size_t)NMAX * 256];
__device__ __align__(16) __half g_Wh[110592];
__device__ __align__(16) __half g_Wlo[110592];
__device__ int g_row_off[NMAX + 1];
__device__ int g_cnt[NMAX];                       // zero-init at module load
__device__ volatile unsigned long long g_pack[64]; // scan aggregates (flag|val)
__device__ int g_src_sorted[EMAX];
__device__ int g_is64;

#define WOFF_PL1 0
#define WOFF_2   12288
#define WOFF_3   45056
#define WTOT     110592

// --------------------------- PTX helpers -----------------------------------
__device__ __forceinline__ void ldm4(unsigned* r, uint32_t addr) {
    asm volatile("ldmatrix.sync.aligned.m8n8.x4.shared.b16 {%0,%1,%2,%3}, [%4];"
                 : "=r"(r[0]), "=r"(r[1]), "=r"(r[2]), "=r"(r[3]) : "r"(addr));
}
__device__ __forceinline__ void cp16(uint32_t d, const void* s, bool p) {
    asm volatile("cp.async.cg.shared.global [%0], [%1], 16, %2;"
                 :: "r"(d), "l"(s), "r"(p ? 16 : 0) : "memory");
}
__device__ __forceinline__ void cpcommit() {
    asm volatile("cp.async.commit_group;" ::: "memory");
}
__device__ __forceinline__ void mma16816(float* c, const unsigned* a,
                                         unsigned b0, unsigned b1) {
    asm volatile(
        "mma.sync.aligned.m16n8k16.row.col.f32.f16.f16.f32 "
        "{%0,%1,%2,%3}, {%4,%5,%6,%7}, {%8,%9}, {%0,%1,%2,%3};"
        : "+f"(c[0]), "+f"(c[1]), "+f"(c[2]), "+f"(c[3])
        : "r"(a[0]), "r"(a[1]), "r"(a[2]), "r"(a[3]), "r"(b0), "r"(b1));
}

// ------ conversion (weights + x) + edge histogram + dtype detect -----------
__global__ void cvt_hist(const float* __restrict__ x, int nx,
                         const void* __restrict__ ev, int E,
                         const float* __restrict__ Wp,
                         const float* __restrict__ Wl1, const float* __restrict__ Wr1,
                         const float* __restrict__ Wl2, const float* __restrict__ Wr2,
                         const float* __restrict__ Wl3, const float* __restrict__ Wr3) {
    int i = blockIdx.x * blockDim.x + threadIdx.x;
    const unsigned int* eu = (const unsigned int*)ev;
    if (i < E) {
        int is64 = 1;
#pragma unroll
        for (int q = 0; q < 8; q++)
            if (eu[2 * q + 1] != 0u) is64 = 0;
        if (i == 0) g_is64 = is64;
        int dst;
        if (is64) dst = (int)((const long long*)ev)[(size_t)E + i];
        else      dst = ((const int*)ev)[E + i];
        atomicAdd(&g_cnt[dst], 1);
    }
    if (i < WTOT) {
        float w;
        if (i < 12288) {
            int n = i / 64, k = i % 64;
            if (n < 64)       w = Wp[k * 64 + n];
            else if (n < 128) w = Wl1[k * 64 + (n - 64)];
            else              w = Wr1[k * 64 + (n - 128)];
        } else if (i < 45056) {
            int j = i - WOFF_2;
            int n = j / 128, k = j % 128;
            w = (n < 128) ? Wl2[k * 128 + n] : Wr2[k * 128 + (n - 128)];
        } else {
            int j = i - WOFF_3;
            int n = j / 256, k = j % 256;
            w = (n < 128) ? Wl3[k * 128 + n] : Wr3[k * 128 + (n - 128)];
        }
        __half hi = __float2half_rn(w);
        g_Wh[i]  = hi;
        g_Wlo[i] = __float2half_rn(w - __half2float(hi));
    } else {
        int j = i - WTOT;
        if (j < nx) g_Xh[j] = __float2half_rn(x[j]);
    }
}

// ---------------- single-pass scan (parallel aggregate lookback) -----------
// Requires gridDim.x <= 64 and all blocks co-resident (49 blocks, 148 SMs).
// g_pack[] must be zero on entry (module load / re-zeroed by final agg).
__global__ void __launch_bounds__(SCAN_B) scan_fused(int n, int E) {
    __shared__ int wsum[32];
    __shared__ int run_sh;
    int tid = threadIdx.x;
    int lane = tid & 31, wid = tid >> 5;
    int b = blockIdx.x;
    int i = b * SCAN_B + tid;
    int v = (i < n) ? g_cnt[i] : 0;
    int incl = v;
#pragma unroll
    for (int off = 1; off < 32; off <<= 1) {
        int t = __shfl_up_sync(0xffffffffu, incl, off);
        if (lane >= off) incl += t;
    }
    if (lane == 31) wsum[wid] = incl;
    __syncthreads();
    if (wid == 0) {
        int w = wsum[lane];
#pragma unroll
        for (int off = 1; off < 32; off <<= 1) {
            int t = __shfl_up_sync(0xffffffffu, w, off);
            if (lane >= off) w += t;
        }
        wsum[lane] = w;
    }
    __syncthreads();
    int add = (wid > 0) ? wsum[wid - 1] : 0;
    int excl = add + incl - v;

    if (tid == 0) run_sh = 0;
    if (tid == SCAN_B - 1) {
        // publish this block's tile total as (flag=1 | value), single word
        g_pack[b] = (1ull << 32) | (unsigned long long)(unsigned)(add + incl);
    }
    __syncthreads();
    if (tid < b) {                    // parallel lookback over predecessors
        unsigned long long p;
        do { p = g_pack[tid]; } while (!(p >> 32));
        atomicAdd(&run_sh, (int)(unsigned)p);
    }
    __syncthreads();
    int run = run_sh;
    if (i < n) {
        int val = run + excl;
        g_row_off[i] = val;
        g_cnt[i] = val;               // cursor for scatter
    }
    if (b == gridDim.x - 1 && tid == 0) g_row_off[n] = E;
}

// 2 edges per thread, vectorized loads
__global__ void scatter_kernel(const void* e, int E) {
    int i = (blockIdx.x * blockDim.x + threadIdx.x) * 2;
    if (i >= E) return;
    bool two = (i + 1 < E);
    int s0, s1, d0, d1;
    if (g_is64) {
        if (two) {
            longlong2 s = *(const longlong2*)&((const long long*)e)[i];
            longlong2 d = *(const longlong2*)&((const long long*)e)[(size_t)E + i];
            s0 = (int)s.x; s1 = (int)s.y; d0 = (int)d.x; d1 = (int)d.y;
        } else {
            s0 = (int)((const long long*)e)[i];
            d0 = (int)((const long long*)e)[(size_t)E + i];
            s1 = d1 = -1;
        }
    } else {
        if (two) {
            int2 s = *(const int2*)&((const int*)e)[i];
            int2 d = *(const int2*)&((const int*)e)[E + i];
            s0 = s.x; s1 = s.y; d0 = d.x; d1 = d.y;
        } else {
            s0 = ((const int*)e)[i];
            d0 = ((const int*)e)[E + i];
            s1 = d1 = -1;
        }
    }
    int p0 = atomicAdd(&g_cnt[d0], 1);
    g_src_sorted[p0] = s0;
    if (two) {
        int p1 = atomicAdd(&g_cnt[d1], 1);
        g_src_sorted[p1] = s1;
    }
}

// --------------------------- tensor-core GEMM ------------------------------
#define SROWB 80
#define ARRB  10240
#define STAGEB 30720
#define GEMM_SMEM (2 * STAGEB)

__global__ void __launch_bounds__(256, 2) gemm_tc_kernel(
    const __half* __restrict__ Ag, int lda,
    const __half* __restrict__ Wh, const __half* __restrict__ Wl,
    const float* __restrict__ bias,
    __half* __restrict__ C1, __half* __restrict__ C2,
    int ldc, int coff, int ldc2, int M, int N, int K, int mode)
{
    extern __shared__ __align__(16) char smem_raw[];
    uint32_t sb0 = (uint32_t)__cvta_generic_to_shared(smem_raw);
    int tid = threadIdx.x, lane = tid & 31, wid = tid >> 5;
    int wm = wid & 3, wn = wid >> 2;
    int g = lane >> 2, t4 = lane & 3;
    int m0 = blockIdx.x << 7, n0 = blockIdx.y << 7;

    uint32_t arowoff[2];
#pragma unroll
    for (int mi = 0; mi < 2; mi++) {
        int r = (wm << 5) + (mi << 4) + (lane & 7) + (((lane >> 3) & 1) << 3);
        arowoff[mi] = (uint32_t)r * SROWB + ((lane >> 4) << 4);
    }
    uint32_t boff[4];
#pragma unroll
    for (int p = 0; p < 4; p++) {
        int r = (wn << 6) + (p << 4) + (lane & 7) + ((lane >> 4) << 3);
        boff[p] = (uint32_t)r * SROWB + (((lane >> 3) & 1) << 4);
    }

    float acc[2][8][4];
#pragma unroll
    for (int mi = 0; mi < 2; mi++)
#pragma unroll
        for (int ni = 0; ni < 8; ni++)
#pragma unroll
            for (int q = 0; q < 4; q++) acc[mi][ni][q] = 0.f;

    auto stage = [&](int kt, int s) {
        int k0 = kt << 5;
        uint32_t sb = sb0 + (uint32_t)s * STAGEB;
#pragma unroll
        for (int h = 0; h < 2; h++) {
            int c = tid + (h << 8);
            int row = c >> 2, part = c & 3;
            uint32_t soff = (uint32_t)row * SROWB + (part << 4);
            int am = m0 + row;
            bool av = am < M; if (!av) am = 0;
            cp16(sb + soff, Ag + (size_t)am * lda + k0 + (part << 3), av);
            int bn = n0 + row;
            bool bv = bn < N; if (!bv) bn = 0;
            size_t woff = (size_t)bn * K + k0 + (part << 3);
            cp16(sb + ARRB + soff,     Wh + woff, bv);
            cp16(sb + 2 * ARRB + soff, Wl + woff, bv);
        }
        cpcommit();
    };

    int KT = K >> 5;
    stage(0, 0);
    for (int kt = 0; kt < KT; kt++) {
        int s = kt & 1;
        if (kt + 1 < KT) {
            stage(kt + 1, s ^ 1);
            asm volatile("cp.async.wait_group 1;" ::: "memory");
        } else {
            asm volatile("cp.async.wait_group 0;" ::: "memory");
        }
        __syncthreads();
        uint32_t sb = sb0 + (uint32_t)s * STAGEB;
#pragma unroll
        for (int ks = 0; ks < 2; ks++) {
            uint32_t ko = (uint32_t)ks << 5;
            unsigned ah[2][4];
            ldm4(ah[0], sb + arowoff[0] + ko);
            ldm4(ah[1], sb + arowoff[1] + ko);
#pragma unroll
            for (int p = 0; p < 4; p++) {
                unsigned bh[4], bl[4];
                ldm4(bh, sb + ARRB + boff[p] + ko);
                ldm4(bl, sb + 2 * ARRB + boff[p] + ko);
                mma16816(acc[0][2 * p],     ah[0], bh[0], bh[1]);
                mma16816(acc[0][2 * p + 1], ah[0], bh[2], bh[3]);
                mma16816(acc[1][2 * p],     ah[1], bh[0], bh[1]);
                mma16816(acc[1][2 * p + 1], ah[1], bh[2], bh[3]);

                mma16816(acc[0][2 * p],     ah[0], bl[0], bl[1]);
                mma16816(acc[0][2 * p + 1], ah[0], bl[2], bl[3]);
                mma16816(acc[1][2 * p],     ah[1], bl[0], bl[1]);
                mma16816(acc[1][2 * p + 1], ah[1], bl[2], bl[3]);
            }
        }
        __syncthreads();
    }

    bool split = (mode & 2) != 0;
    bool relu = (mode & 1) != 0;
#pragma unroll
    for (int mi = 0; mi < 2; mi++) {
#pragma unroll
        for (int ni = 0; ni < 8; ni++) {
            int row = m0 + (wm << 5) + (mi << 4) + g;
            int col = n0 + (wn << 6) + (ni << 3) + (t4 << 1);
            if (col >= N) continue;
#pragma unroll
            for (int hh = 0; hh < 2; hh++) {
                int r = row + hh * 8;
                if (r >= M) continue;
                float vx = acc[mi][ni][2 * hh];
                float vy = acc[mi][ni][2 * hh + 1];
                if (split) {
                    if (col < 64) {
                        vx = fmaxf(vx + bias[col], 0.f);
                        vy = fmaxf(vy + bias[col + 1], 0.f);
                        *(__half2*)&C1[(size_t)r * ldc + coff + col] =
                            __halves2half2(__float2half_rn(vx),
                                           __float2half_rn(vy));
                    } else {
                        *(__half2*)&C2[(size_t)r * ldc2 + (col - 64)] =
                            __halves2half2(__float2half_rn(vx),
                                           __float2half_rn(vy));
                    }
                } else {
                    if (bias) { vx += bias[col]; vy += bias[col + 1]; }
                    if (relu) { vx = fmaxf(vx, 0.f); vy = fmaxf(vy, 0.f); }
                    *(__half2*)&C1[(size_t)r * ldc + coff + col] =
                        __halves2half2(__float2half_rn(vx),
                                       __float2half_rn(vy));
                }
            }
        }
    }
}

// ------------------------------ aggregation (fp16 Y) -----------------------
// zero_n > 0 (final layer only): re-zero g_cnt[0:zero_n) and g_pack for the
// next launch (after scatter; deterministic across graph replays).
template <int V>
__global__ void agg_h_kernel(const __half* __restrict__ Y, int ldy, int ycol,
                             int rcol, const float* __restrict__ bias,
                             float* __restrict__ Of, __half* __restrict__ Oh,
                             int ldo, int ocol, int Nn, int zero_n)
{
    int gt = blockIdx.x * blockDim.x + threadIdx.x;
    if (zero_n) {
        if (gt < 64) ((volatile unsigned long long*)g_pack)[gt] = 0ull;
        if (gt < zero_n) g_cnt[gt] = 0;
    }
    int gw = gt >> 5;
    int lane = threadIdx.x & 31;
    if (gw >= Nn) return;
    int s0 = g_row_off[gw], s1 = g_row_off[gw + 1];
    int col = lane * V;
    float acc[V];
#pragma unroll
    for (int v = 0; v < V; v++) acc[v] = 0.f;
    const __half* Yb = Y + ycol + col;

    auto addrow = [&](const __half* p) {
        if (V == 4) {
            uint2 u = *(const uint2*)p;
            float2 f0 = __half22float2(*(__half2*)&u.x);
            float2 f1 = __half22float2(*(__half2*)&u.y);
            acc[0] += f0.x; acc[1] += f0.y; acc[2] += f1.x; acc[3] += f1.y;
        } else {
            float2 f = __half22float2(*(const __half2*)p);
            acc[0] += f.x; acc[1] += f.y;
        }
    };

    int j = s0;
    for (; j + 7 < s1; j += 8) {
        int s[8];
#pragma unroll
        for (int q = 0; q < 8; q++) s[q] = g_src_sorted[j + q];
#pragma unroll
        for (int q = 0; q < 8; q++) addrow(Yb + (size_t)s[q] * ldy);
    }
    for (; j + 3 < s1; j += 4) {
        int s[4];
#pragma unroll
        for (int q = 0; q < 4; q++) s[q] = g_src_sorted[j + q];
#pragma unroll
        for (int q = 0; q < 4; q++) addrow(Yb + (size_t)s[q] * ldy);
    }
    for (; j < s1; j++) addrow(Yb + (size_t)g_src_sorted[j] * ldy);

    int deg = s1 - s0;
    float inv = 1.f / (float)(deg > 1 ? deg : 1);

    float rterm[V];
    {
        const __half* p = Y + (size_t)gw * ldy + rcol + col;
        if (V == 4) {
            uint2 u = *(const uint2*)p;
            float2 f0 = __half22float2(*(__half2*)&u.x);
            float2 f1 = __half22float2(*(__half2*)&u.y);
            rterm[0] = f0.x; rterm[1] = f0.y; rterm[2] = f1.x; rterm[3] = f1.y;
        } else {
            float2 f = __half22float2(*(const __half2*)p);
            rterm[0] = f.x; rterm[1] = f.y;
        }
    }

    float o[V];
#pragma unroll
    for (int v = 0; v < V; v++)
        o[v] = fmaxf(acc[v] * inv + rterm[v] + bias[col + v], 0.f);

    size_t off = (size_t)gw * ldo + ocol + col;
    if (Oh) {
#pragma unroll
        for (int v = 0; v < V; v += 2)
            *(__half2*)&Oh[off + v] =
                __halves2half2(__float2half_rn(o[v]), __float2half_rn(o[v + 1]));
    } else {
        if (V == 4)
            *(float4*)&Of[off] = make_float4(o[0], o[1], o[2], o[3]);
        else
            *(float2*)&Of[off] = make_float2(o[0], o[1]);
    }
}

// ------------------------------- launcher ----------------------------------
extern "C" void kernel_launch(void* const* d_in, const int* in_sizes, int n_in,
                              void* d_out, int out_size)
{
    const float* x   = (const float*)d_in[0];
    const void*  eix = d_in[1];
    const float* Wp  = (const float*)d_in[2];
    const float* bp  = (const float*)d_in[3];
    const float* Wl1 = (const float*)d_in[4];
    const float* bl1 = (const float*)d_in[5];
    const float* Wr1 = (const float*)d_in[6];
    const float* Wl2 = (const float*)d_in[7];
    const float* bl2 = (const float*)d_in[8];
    const float* Wr2 = (const float*)d_in[9];
    const float* Wl3 = (const float*)d_in[10];
    const float* bl3 = (const float*)d_in[11];
    const float* Wr3 = (const float*)d_in[12];

    int N = in_sizes[0] / 64;
    int E = in_sizes[1] / 2;
    float* out = (float*)d_out;

    __half *dYh, *dXh, *dFh, *dWh, *dWlo;
    cudaGetSymbolAddress((void**)&dYh, g_Yh);
    cudaGetSymbolAddress((void**)&dXh, g_Xh);
    cudaGetSymbolAddress((void**)&dFh, g_Fh);
    cudaGetSymbolAddress((void**)&dWh, g_Wh);
    cudaGetSymbolAddress((void**)&dWlo, g_Wlo);

    cudaFuncSetAttribute(gemm_tc_kernel,
                         cudaFuncAttributeMaxDynamicSharedMemorySize,
                         GEMM_SMEM);

    int nb = (N + SCAN_B - 1) / SCAN_B;   // 49 <= 64, all co-resident
    int mg = (N + 127) / 128;
    int ne2 = (E + 1) / 2;

    // ---- conversions + histogram (g_cnt pre-zeroed by prior run / load) ----
    int ncvt = WTOT + N * 64;
    if (ncvt < E) ncvt = E;
    cvt_hist<<<(ncvt + 255) / 256, 256>>>(x, N * 64, eix, E,
                                          Wp, Wl1, Wr1, Wl2, Wr2, Wl3, Wr3);

    // ---- fused layer-1 GEMM: [xp | y1 | r1] = x @ [Wp|Wl1|Wr1], N=192 ----
    gemm_tc_kernel<<<dim3(mg, 2), 256, GEMM_SMEM>>>(
        dXh, 64, dWh + WOFF_PL1, dWlo + WOFF_PL1, bp,
        dFh, dYh, 256, 0, 256, N, 192, 64, 2);

    // ---- CSR: single-pass scan + scatter ----
    scan_fused<<<nb, SCAN_B>>>(N, E);
    scatter_kernel<<<(ne2 + 255) / 256, 256>>>(eix, E);

    // ---- layer 1 aggregation -> Fh[:,64:128] ----
    agg_h_kernel<2><<<(N + 7) / 8, 256>>>(dYh, 256, 0, 64, bl1,
                                          nullptr, dFh, 256, 64, N, 0);

    // ---- layer 2 ----
    gemm_tc_kernel<<<dim3(mg, 2), 256, GEMM_SMEM>>>(
        dFh, 256, dWh + WOFF_2, dWlo + WOFF_2, nullptr,
        dYh, nullptr, 256, 0, 0, N, 256, 128, 0);
    agg_h_kernel<4><<<(N + 7) / 8, 256>>>(dYh, 256, 0, 128, bl2,
                                          nullptr, dFh, 256, 128, N, 0);

    // ---- layer 3 (final agg re-zeroes g_cnt / g_pack for next launch) ----
    gemm_tc_kernel<<<dim3(mg, 2), 256, GEMM_SMEM>>>(
        dFh, 256, dWh + WOFF_3, dWlo + WOFF_3, nullptr,
        dYh, nullptr, 256, 0, 0, N, 256, 256, 0);
    agg_h_kernel<4><<<(N + 7) / 8, 256>>>(dYh, 256, 0, 128, bl3,
                                          out, nullptr, 128, 0, N, N);
}